// round 8
// baseline (speedup 1.0000x reference)
#include <cuda_runtime.h>
#include <math_constants.h>

// RoIPool: feature_map [B=2, H=50, W=50, C=256] f32, rpn_pred [B=2, N=128, 4] f32
// out [B, N, 7, 7, C] f32.
//   x1=(int)(W*p0); y1=(int)(H*p1); x2=(int)(W*p2); y2=(int)(H*p3)
//   sw=(x2-x1)/7; sh=(y2-y1)/7   (in [1,4] by input construction)
//   out[b,n,i,j,c] = max_{r<sh,t<sw} fm[b, y1+i*sh+r, x1+j*sw+t, c]
// Bounds: x1+7*sw-1 <= x2-1 <= 49 (same for y) -> reference clip is dead code.
//
// R8: CTA = 320 threads = 5 slots x (bin-pair); each thread processes its
// bin-pair for TWO ROIs (n and n+64). Grid (5,64,2) = 640 CTAs <= 148*5 CTA
// capacity -> exactly ONE wave, no tail. Two independent ROI chains per
// thread (~24 in-flight gathers) halve serial latency exposures.
// __launch_bounds__(320,5) pins regs <= 40 so 5 CTAs/SM residency holds.

#define POOL 7
#define NROIS 128
#define BB 2
#define HH 50
#define WW 50
#define CC 256
#define C4 (CC / 4)   // 64 float4 per pixel
#define NBINS (POOL * POOL)       // 49
#define NPAIR ((NBINS + 1) / 2)   // 25
#define SLOTS 5
#define THREADS (SLOTS * 64)      // 320
#define NHALF (NROIS / 2)         // 64

__device__ __forceinline__ void fmax4(float4& m, const float4 v) {
    m.x = fmaxf(m.x, v.x);
    m.y = fmaxf(m.y, v.y);
    m.z = fmaxf(m.z, v.z);
    m.w = fmaxf(m.w, v.w);
}

// Exact SHxSW window max for two bins. All offsets compile-time immediates.
template<int SH, int SW>
__device__ __forceinline__ void window_pair(const float4* __restrict__ base0,
                                            const float4* __restrict__ base1,
                                            float4& m0, float4& m1) {
    #pragma unroll
    for (int r = 0; r < SH; ++r) {
        float4 a0[SW], a1[SW];
        #pragma unroll
        for (int t = 0; t < SW; ++t) {
            a0[t] = __ldg(base0 + (r * WW + t) * C4);
            a1[t] = __ldg(base1 + (r * WW + t) * C4);
        }
        #pragma unroll
        for (int t = 0; t < SW; ++t) {
            fmax4(m0, a0[t]);
            fmax4(m1, a1[t]);
        }
    }
}

// Warp-uniform 16-way dispatch on (sh,sw).
__device__ __forceinline__ void dispatch_pair(int code,
                                              const float4* __restrict__ base0,
                                              const float4* __restrict__ base1,
                                              float4& m0, float4& m1) {
    switch (code) {
        case  0: window_pair<1,1>(base0, base1, m0, m1); break;
        case  1: window_pair<1,2>(base0, base1, m0, m1); break;
        case  2: window_pair<1,3>(base0, base1, m0, m1); break;
        case  3: window_pair<1,4>(base0, base1, m0, m1); break;
        case  4: window_pair<2,1>(base0, base1, m0, m1); break;
        case  5: window_pair<2,2>(base0, base1, m0, m1); break;
        case  6: window_pair<2,3>(base0, base1, m0, m1); break;
        case  7: window_pair<2,4>(base0, base1, m0, m1); break;
        case  8: window_pair<3,1>(base0, base1, m0, m1); break;
        case  9: window_pair<3,2>(base0, base1, m0, m1); break;
        case 10: window_pair<3,3>(base0, base1, m0, m1); break;
        case 11: window_pair<3,4>(base0, base1, m0, m1); break;
        case 12: window_pair<4,1>(base0, base1, m0, m1); break;
        case 13: window_pair<4,2>(base0, base1, m0, m1); break;
        case 14: window_pair<4,3>(base0, base1, m0, m1); break;
        default: window_pair<4,4>(base0, base1, m0, m1); break;
    }
}

__global__ __launch_bounds__(THREADS, 5) void roi_pool_kernel(
    const float4* __restrict__ fm,     // [B*H*W*C4] float4
    const float4* __restrict__ rois,   // [B*N] float4 (x1,y1,x2,y2)
    float4*       __restrict__ out)    // [B*N*49*C4] float4
{
    const int slot = threadIdx.x >> 6;          // 0..4
    const int c4   = threadIdx.x & 63;          // 0..63 -> 4 channels
    const int pb   = blockIdx.x * SLOTS + slot; // 0..24 bin pair
    const int nA   = blockIdx.y;                // ROI A
    const int nB   = nA + NHALF;                // ROI B
    const int b    = blockIdx.z;                // batch

    const int bin0 = pb * 2;
    const int bin1 = bin0 + 1;
    const bool has1 = (bin1 < NBINS);

    // Both ROI descriptor loads in flight immediately (independent).
    const float4 rpA = __ldg(rois + b * NROIS + nA);
    const float4 rpB = __ldg(rois + b * NROIS + nB);

    const int x1A = (int)(WW * rpA.x), y1A = (int)(HH * rpA.y);
    const int swA = ((int)(WW * rpA.z) - x1A) / POOL;
    const int shA = ((int)(HH * rpA.w) - y1A) / POOL;
    const int x1B = (int)(WW * rpB.x), y1B = (int)(HH * rpB.y);
    const int swB = ((int)(WW * rpB.z) - x1B) / POOL;
    const int shB = ((int)(HH * rpB.w) - y1B) / POOL;

    const int i0 = bin0 / POOL, j0 = bin0 - i0 * POOL;
    const int i1 = bin1 / POOL, j1 = bin1 - i1 * POOL;

    const float4* fmb = fm + (b * HH * WW) * C4 + c4;

    const float4* a0 = fmb + ((y1A + i0 * shA) * WW + (x1A + j0 * swA)) * C4;
    const float4* a1 = has1 ? fmb + ((y1A + i1 * shA) * WW + (x1A + j1 * swA)) * C4 : a0;
    const float4* b0 = fmb + ((y1B + i0 * shB) * WW + (x1B + j0 * swB)) * C4;
    const float4* b1 = has1 ? fmb + ((y1B + i1 * shB) * WW + (x1B + j1 * swB)) * C4 : b0;

    const float NEG = -CUDART_INF_F;
    float4 mA0 = make_float4(NEG, NEG, NEG, NEG);
    float4 mA1 = make_float4(NEG, NEG, NEG, NEG);
    float4 mB0 = make_float4(NEG, NEG, NEG, NEG);
    float4 mB1 = make_float4(NEG, NEG, NEG, NEG);

    dispatch_pair((shA - 1) * 4 + (swA - 1), a0, a1, mA0, mA1);
    dispatch_pair((shB - 1) * 4 + (swB - 1), b0, b1, mB0, mB1);

    float4* oA = out + ((b * NROIS + nA) * NBINS + bin0) * C4 + c4;
    float4* oB = out + ((b * NROIS + nB) * NBINS + bin0) * C4 + c4;
    oA[0] = mA0;
    oB[0] = mB0;
    if (has1) {
        oA[C4] = mA1;
        oB[C4] = mB1;
    }
}

extern "C" void kernel_launch(void* const* d_in, const int* in_sizes, int n_in,
                              void* d_out, int out_size) {
    const float4* fm   = (const float4*)d_in[0];  // feature_map
    const float4* rois = (const float4*)d_in[1];  // rpn_pred as float4
    float4*       out  = (float4*)d_out;

    dim3 grid(NPAIR / SLOTS, NHALF, BB);          // 5 x 64 x 2 = 640 CTAs
    roi_pool_kernel<<<grid, THREADS>>>(fm, rois, out);
}